// round 6
// baseline (speedup 1.0000x reference)
#include <cuda_runtime.h>
#include <cuda_fp16.h>
#include <cstdint>

#define S_LEN 2048
#define B_SZ 2
#define DM 1024
#define NH 16
#define DK 64
#define ROWS (B_SZ * S_LEN)   // 4096

// ---------------------------------------------------------------------------
// Scratch (allocation-free __device__ globals)
// ---------------------------------------------------------------------------
__device__ __align__(16) __half g_qh[(size_t)ROWS * DM];
__device__ __align__(16) __half g_kh[(size_t)ROWS * DM];
__device__ __align__(16) __half g_vh[(size_t)ROWS * DM];
__device__ __align__(16) __half g_Wqh[(size_t)DM * DM];
__device__ __align__(16) __half g_Wkh[(size_t)DM * DM];
__device__ __align__(16) __half g_Wvh[(size_t)DM * DM];
__device__ __align__(16) __half g_Woh[(size_t)DM * DM];
__device__ __align__(16) __half g_Qh[(size_t)ROWS * DM];
__device__ __align__(16) __half g_Kh[(size_t)ROWS * DM];
__device__ __align__(16) __half g_Vh[(size_t)ROWS * DM];
__device__ __align__(16) __half g_Ch[(size_t)ROWS * DM];

// ---------------------------------------------------------------------------
// PTX helpers
// ---------------------------------------------------------------------------
__device__ __forceinline__ uint32_t sptr(const void* p) {
    return (uint32_t)__cvta_generic_to_shared(p);
}
__device__ __forceinline__ void ldm_x4(uint32_t& r0, uint32_t& r1,
                                       uint32_t& r2, uint32_t& r3, uint32_t a) {
    asm volatile("ldmatrix.sync.aligned.m8n8.x4.shared.b16 {%0,%1,%2,%3},[%4];\n"
                 : "=r"(r0), "=r"(r1), "=r"(r2), "=r"(r3) : "r"(a));
}
__device__ __forceinline__ void ldm_x4_t(uint32_t& r0, uint32_t& r1,
                                         uint32_t& r2, uint32_t& r3, uint32_t a) {
    asm volatile("ldmatrix.sync.aligned.m8n8.x4.trans.shared.b16 {%0,%1,%2,%3},[%4];\n"
                 : "=r"(r0), "=r"(r1), "=r"(r2), "=r"(r3) : "r"(a));
}
__device__ __forceinline__ void mma16816(float* c, const uint32_t* a,
                                         uint32_t b0, uint32_t b1) {
    asm volatile(
        "mma.sync.aligned.m16n8k16.row.col.f32.f16.f16.f32 "
        "{%0,%1,%2,%3},{%4,%5,%6,%7},{%8,%9},{%0,%1,%2,%3};\n"
        : "+f"(c[0]), "+f"(c[1]), "+f"(c[2]), "+f"(c[3])
        : "r"(a[0]), "r"(a[1]), "r"(a[2]), "r"(a[3]), "r"(b0), "r"(b1));
}
__device__ __forceinline__ uint32_t pack_h2(float x, float y) {
    __half2 h = __floats2half2_rn(x, y);
    return *reinterpret_cast<uint32_t*>(&h);
}
__device__ __forceinline__ void cp16(uint32_t dst, const void* src) {
    asm volatile("cp.async.cg.shared.global [%0],[%1],16;\n" :: "r"(dst), "l"(src));
}
__device__ __forceinline__ void cp_commit() {
    asm volatile("cp.async.commit_group;\n");
}
template <int N>
__device__ __forceinline__ void cp_wait() {
    asm volatile("cp.async.wait_group %0;\n" :: "n"(N));
}
__device__ __forceinline__ float ex2(float x) {
    float y;
    asm("ex2.approx.f32 %0,%1;" : "=f"(y) : "f"(x));
    return y;
}

// ---------------------------------------------------------------------------
// Fused fp32 -> fp16 conversion for all 7 arrays in ONE launch.
// Layout: 3 activation arrays of 2^20 float4 each, then 4 weights of 2^18.
// ---------------------------------------------------------------------------
struct ConvArgs {
    const float4* src[7];
    __half2* dst[7];
};
#define ACT4 (1u << 20)     // ROWS*DM/4
#define W4   (1u << 18)     // DM*DM/4
#define CONV_TOT (3 * ACT4 + 4 * W4)

__global__ __launch_bounds__(256) void f2h_all(ConvArgs a) {
    const uint32_t stride = gridDim.x * blockDim.x;
    for (uint32_t i = blockIdx.x * blockDim.x + threadIdx.x; i < CONV_TOT;
         i += stride) {
        int j; uint32_t off;
        if (i < 3 * ACT4) { j = i >> 20; off = i & (ACT4 - 1); }
        else { uint32_t t = i - 3 * ACT4; j = 3 + (t >> 18); off = t & (W4 - 1); }
        float4 v = a.src[j][off];
        a.dst[j][2 * off]     = __floats2half2_rn(v.x, v.y);
        a.dst[j][2 * off + 1] = __floats2half2_rn(v.z, v.w);
    }
}

// ---------------------------------------------------------------------------
// HMMA GEMM with fused bias (R2-proven config).
// C[m][n] = sum_k A[m][k]*W[n][k] + bias[n].  CTA tile 128x128, BK=64,
// 8 warps (2m x 4n), warp tile 64x32, m16n8k16, fp32 accum.
// QKV3: grid.z selects (A, W, bias, out) -> one launch for all projections.
// ---------------------------------------------------------------------------
struct Gemm3Args {
    const __half* A[3];
    const __half* W[3];
    const float* bias[3];
    __half* out[3];
};

template <bool HALF_OUT>
__device__ __forceinline__ void gemm_body(
    const __half* __restrict__ A, const __half* __restrict__ W,
    const float* __restrict__ bias, void* __restrict__ Cout,
    int M, int N, int K)
{
    __shared__ __half As[128 * 72];
    __shared__ __half Ws[128 * 72];

    const int tid = threadIdx.x;
    const int warp = tid >> 5, lane = tid & 31;
    const int wm = warp >> 2;
    const int wn = warp & 3;
    const int row0 = blockIdx.y * 128;
    const int col0 = blockIdx.x * 128;

    float acc[4][4][4];
    #pragma unroll
    for (int i = 0; i < 4; i++)
        #pragma unroll
        for (int j = 0; j < 4; j++)
            #pragma unroll
            for (int r = 0; r < 4; r++) acc[i][j][r] = 0.0f;

    const int srow = tid >> 3;
    const int scol = (tid & 7) * 8;

    for (int k0 = 0; k0 < K; k0 += 64) {
        #pragma unroll
        for (int i = 0; i < 4; i++) {
            const int r = srow + i * 32;
            *(uint4*)&As[r * 72 + scol] =
                *(const uint4*)&A[(size_t)(row0 + r) * K + k0 + scol];
            *(uint4*)&Ws[r * 72 + scol] =
                *(const uint4*)&W[(size_t)(col0 + r) * K + k0 + scol];
        }
        __syncthreads();

        #pragma unroll
        for (int kk = 0; kk < 64; kk += 16) {
            uint32_t af[4][4];
            #pragma unroll
            for (int mt = 0; mt < 4; mt++) {
                const int r = wm * 64 + mt * 16 + (lane & 15);
                const int c = kk + ((lane >> 4) << 3);
                ldm_x4(af[mt][0], af[mt][1], af[mt][2], af[mt][3],
                       sptr(&As[r * 72 + c]));
            }
            uint32_t bf[4][2];
            #pragma unroll
            for (int nt = 0; nt < 4; nt += 2) {
                const int g = lane >> 3;
                const int rr = wn * 32 + nt * 8 + ((g >= 2) ? 8 : 0) + (lane & 7);
                const int cc = kk + ((g & 1) << 3);
                ldm_x4(bf[nt][0], bf[nt][1], bf[nt + 1][0], bf[nt + 1][1],
                       sptr(&Ws[rr * 72 + cc]));
            }
            #pragma unroll
            for (int mt = 0; mt < 4; mt++)
                #pragma unroll
                for (int nt = 0; nt < 4; nt++)
                    mma16816(acc[mt][nt], af[mt], bf[nt][0], bf[nt][1]);
        }
        __syncthreads();
    }

    #pragma unroll
    for (int mt = 0; mt < 4; mt++) {
        const int r = row0 + wm * 64 + mt * 16 + (lane >> 2);
        #pragma unroll
        for (int nt = 0; nt < 4; nt++) {
            const int c = col0 + wn * 32 + nt * 8 + ((lane & 3) << 1);
            const float b0 = bias[c], b1 = bias[c + 1];
            if (HALF_OUT) {
                __half* C = (__half*)Cout;
                *(__half2*)&C[(size_t)r * N + c] =
                    __floats2half2_rn(acc[mt][nt][0] + b0, acc[mt][nt][1] + b1);
                *(__half2*)&C[(size_t)(r + 8) * N + c] =
                    __floats2half2_rn(acc[mt][nt][2] + b0, acc[mt][nt][3] + b1);
            } else {
                float* C = (float*)Cout;
                float2 v0 = {acc[mt][nt][0] + b0, acc[mt][nt][1] + b1};
                float2 v1 = {acc[mt][nt][2] + b0, acc[mt][nt][3] + b1};
                *(float2*)&C[(size_t)r * N + c] = v0;
                *(float2*)&C[(size_t)(r + 8) * N + c] = v1;
            }
        }
    }
}

__global__ __launch_bounds__(256) void gemm_qkv3(Gemm3Args ga) {
    const int z = blockIdx.z;
    gemm_body<true>(ga.A[z], ga.W[z], ga.bias[z], ga.out[z], ROWS, DM, DM);
}

__global__ __launch_bounds__(256) void gemm_out(
    const __half* __restrict__ A, const __half* __restrict__ W,
    const float* __restrict__ bias, float* __restrict__ C)
{
    gemm_body<false>(A, W, bias, C, ROWS, DM, DM);
}

// ---------------------------------------------------------------------------
// Flash attention, HMMA, cp.async double-buffered K/V (R3-proven).
// CTA = 128 queries x 1 head (8 warps x 16 q). 64-key tiles, 2 smem stages.
// ---------------------------------------------------------------------------
#define FL_QS   (128 * 72)
#define FL_KVS  (64 * 72)
#define FL_SMEM ((FL_QS + 4 * FL_KVS) * 2)   // 55296 bytes

__global__ __launch_bounds__(256) void flash_attn_tc(
    const __half* __restrict__ Qm, const __half* __restrict__ Km,
    const __half* __restrict__ Vm, __half* __restrict__ Om)
{
    extern __shared__ __align__(1024) char smraw[];
    __half* fsm = (__half*)smraw;
    __half* Qs = fsm;
    __half* Ks = fsm + FL_QS;
    __half* Vs = fsm + FL_QS + 2 * FL_KVS;

    const int tid = threadIdx.x;
    const int warp = tid >> 5, lane = tid & 31;
    const int h = blockIdx.y, b = blockIdx.z;
    const int q0 = blockIdx.x * 128;
    const size_t base = (size_t)b * S_LEN * DM + (size_t)h * DK;
    const float C = 0.125f * 1.4426950408889634f;

    const int kvr = tid >> 2;
    const int kvc = (tid & 3) * 8;
    auto stage_kv = [&](int st, int k0) {
        #pragma unroll
        for (int i = 0; i < 2; i++) {
            const int cc = kvc + i * 32;
            cp16(sptr(&Ks[st * FL_KVS + kvr * 72 + cc]),
                 &Km[base + (size_t)(k0 + kvr) * DM + cc]);
            cp16(sptr(&Vs[st * FL_KVS + kvr * 72 + cc]),
                 &Vm[base + (size_t)(k0 + kvr) * DM + cc]);
        }
        cp_commit();
    };

    stage_kv(0, 0);
    stage_kv(1, 64);

    {
        const int r = tid >> 1;
        const int c0 = (tid & 1) * 32;
        #pragma unroll
        for (int i = 0; i < 4; i++) {
            const int c = c0 + i * 8;
            *(uint4*)&Qs[r * 72 + c] =
                *(const uint4*)&Qm[base + (size_t)(q0 + r) * DM + c];
        }
    }
    __syncthreads();
    uint32_t qf[4][4];
    #pragma unroll
    for (int ks = 0; ks < 4; ks++) {
        const int r = warp * 16 + (lane & 15);
        const int c = ks * 16 + ((lane >> 4) << 3);
        ldm_x4(qf[ks][0], qf[ks][1], qf[ks][2], qf[ks][3], sptr(&Qs[r * 72 + c]));
    }

    float m_[2] = {-1e30f, -1e30f};
    float l_[2] = {0.0f, 0.0f};
    float o[8][4];
    #pragma unroll
    for (int nt = 0; nt < 8; nt++)
        #pragma unroll
        for (int r = 0; r < 4; r++) o[nt][r] = 0.0f;

    const int NT = S_LEN / 64;

    for (int t = 0; t < NT; t++) {
        cp_wait<1>();
        __syncthreads();
        const int st = t & 1;
        const __half* K_ = Ks + st * FL_KVS;
        const __half* V_ = Vs + st * FL_KVS;

        float s[8][4];
        #pragma unroll
        for (int nt = 0; nt < 8; nt++)
            #pragma unroll
            for (int r = 0; r < 4; r++) s[nt][r] = 0.0f;

        #pragma unroll
        for (int ks = 0; ks < 4; ks++) {
            #pragma unroll
            for (int nt = 0; nt < 8; nt += 2) {
                uint32_t b0, b1, b2, b3;
                const int g = lane >> 3;
                const int rr = nt * 8 + ((g >= 2) ? 8 : 0) + (lane & 7);
                const int cc = ks * 16 + ((g & 1) << 3);
                ldm_x4(b0, b1, b2, b3, sptr(&K_[rr * 72 + cc]));
                mma16816(s[nt], qf[ks], b0, b1);
                mma16816(s[nt + 1], qf[ks], b2, b3);
            }
        }

        float mx0 = -1e30f, mx1 = -1e30f;
        #pragma unroll
        for (int nt = 0; nt < 8; nt++) {
            mx0 = fmaxf(mx0, fmaxf(s[nt][0], s[nt][1]));
            mx1 = fmaxf(mx1, fmaxf(s[nt][2], s[nt][3]));
        }
        #pragma unroll
        for (int off = 1; off <= 2; off <<= 1) {
            mx0 = fmaxf(mx0, __shfl_xor_sync(0xffffffffu, mx0, off));
            mx1 = fmaxf(mx1, __shfl_xor_sync(0xffffffffu, mx1, off));
        }
        const float mn0 = fmaxf(m_[0], mx0);
        const float mn1 = fmaxf(m_[1], mx1);
        const float f0 = ex2((m_[0] - mn0) * C);
        const float f1 = ex2((m_[1] - mn1) * C);
        const float mc0 = mn0 * C, mc1 = mn1 * C;
        float sum0 = 0.0f, sum1 = 0.0f;
        #pragma unroll
        for (int nt = 0; nt < 8; nt++) {
            s[nt][0] = ex2(fmaf(s[nt][0], C, -mc0)); sum0 += s[nt][0];
            s[nt][1] = ex2(fmaf(s[nt][1], C, -mc0)); sum0 += s[nt][1];
            s[nt][2] = ex2(fmaf(s[nt][2], C, -mc1)); sum1 += s[nt][2];
            s[nt][3] = ex2(fmaf(s[nt][3], C, -mc1)); sum1 += s[nt][3];
        }
        #pragma unroll
        for (int off = 1; off <= 2; off <<= 1) {
            sum0 += __shfl_xor_sync(0xffffffffu, sum0, off);
            sum1 += __shfl_xor_sync(0xffffffffu, sum1, off);
        }
        l_[0] = l_[0] * f0 + sum0;
        l_[1] = l_[1] * f1 + sum1;
        m_[0] = mn0; m_[1] = mn1;
        #pragma unroll
        for (int nt = 0; nt < 8; nt++) {
            o[nt][0] *= f0; o[nt][1] *= f0;
            o[nt][2] *= f1; o[nt][3] *= f1;
        }

        #pragma unroll
        for (int kt = 0; kt < 4; kt++) {
            uint32_t pa[4];
            pa[0] = pack_h2(s[2 * kt][0],     s[2 * kt][1]);
            pa[1] = pack_h2(s[2 * kt][2],     s[2 * kt][3]);
            pa[2] = pack_h2(s[2 * kt + 1][0], s[2 * kt + 1][1]);
            pa[3] = pack_h2(s[2 * kt + 1][2], s[2 * kt + 1][3]);
            #pragma unroll
            for (int nt = 0; nt < 8; nt += 2) {
                uint32_t b0, b1, b2, b3;
                const int g = lane >> 3;
                const int rr = kt * 16 + ((g & 1) << 3) + (lane & 7);
                const int cc = nt * 8 + ((g >= 2) ? 8 : 0);
                ldm_x4_t(b0, b1, b2, b3, sptr(&V_[rr * 72 + cc]));
                mma16816(o[nt], pa, b0, b1);
                mma16816(o[nt + 1], pa, b2, b3);
            }
        }

        __syncthreads();
        if (t + 2 < NT) stage_kv(st, (t + 2) * 64);
        else cp_commit();
    }

    const float inv0 = 1.0f / l_[0];
    const float inv1 = 1.0f / l_[1];
    const int r = q0 + warp * 16 + (lane >> 2);
    #pragma unroll
    for (int nt = 0; nt < 8; nt++) {
        const int c = nt * 8 + ((lane & 3) << 1);
        *(__half2*)&Om[base + (size_t)r * DM + c] =
            __floats2half2_rn(o[nt][0] * inv0, o[nt][1] * inv0);
        *(__half2*)&Om[base + (size_t)(r + 8) * DM + c] =
            __floats2half2_rn(o[nt][2] * inv1, o[nt][3] * inv1);
    }
}

// ---------------------------------------------------------------------------
// Launch: conv (1) -> fused QKV proj (1) -> flash (1) -> out GEMM (1).
// ---------------------------------------------------------------------------
extern "C" void kernel_launch(void* const* d_in, const int* in_sizes, int n_in,
                              void* d_out, int out_size)
{
    const float* q  = (const float*)d_in[0];
    const float* k  = (const float*)d_in[1];
    const float* v  = (const float*)d_in[2];
    const float* Wq = (const float*)d_in[3];
    const float* bq = (const float*)d_in[4];
    const float* Wk = (const float*)d_in[5];
    const float* bk = (const float*)d_in[6];
    const float* Wv = (const float*)d_in[7];
    const float* bv = (const float*)d_in[8];
    const float* Wo = (const float*)d_in[9];
    const float* bo = (const float*)d_in[10];
    float* out = (float*)d_out;

    __half *qh, *kh, *vh, *Wqh, *Wkh, *Wvh, *Woh, *Qh, *Kh, *Vh, *Ch;
    cudaGetSymbolAddress((void**)&qh,  g_qh);
    cudaGetSymbolAddress((void**)&kh,  g_kh);
    cudaGetSymbolAddress((void**)&vh,  g_vh);
    cudaGetSymbolAddress((void**)&Wqh, g_Wqh);
    cudaGetSymbolAddress((void**)&Wkh, g_Wkh);
    cudaGetSymbolAddress((void**)&Wvh, g_Wvh);
    cudaGetSymbolAddress((void**)&Woh, g_Woh);
    cudaGetSymbolAddress((void**)&Qh,  g_Qh);
    cudaGetSymbolAddress((void**)&Kh,  g_Kh);
    cudaGetSymbolAddress((void**)&Vh,  g_Vh);
    cudaGetSymbolAddress((void**)&Ch,  g_Ch);

    static bool attr_done = false;
    if (!attr_done) {
        cudaFuncSetAttribute(flash_attn_tc,
                             cudaFuncAttributeMaxDynamicSharedMemorySize, FL_SMEM);
        attr_done = true;
    }

    // 1) all conversions in one launch
    ConvArgs ca;
    ca.src[0] = (const float4*)q;  ca.dst[0] = (__half2*)qh;
    ca.src[1] = (const float4*)k;  ca.dst[1] = (__half2*)kh;
    ca.src[2] = (const float4*)v;  ca.dst[2] = (__half2*)vh;
    ca.src[3] = (const float4*)Wq; ca.dst[3] = (__half2*)Wqh;
    ca.src[4] = (const float4*)Wk; ca.dst[4] = (__half2*)Wkh;
    ca.src[5] = (const float4*)Wv; ca.dst[5] = (__half2*)Wvh;
    ca.src[6] = (const float4*)Wo; ca.dst[6] = (__half2*)Woh;
    f2h_all<<<2368, 256>>>(ca);     // 148 SMs * 16 blocks

    // 2) fused Q/K/V projections
    Gemm3Args ga;
    ga.A[0] = qh; ga.W[0] = Wqh; ga.bias[0] = bq; ga.out[0] = Qh;
    ga.A[1] = kh; ga.W[1] = Wkh; ga.bias[1] = bk; ga.out[1] = Kh;
    ga.A[2] = vh; ga.W[2] = Wvh; ga.bias[2] = bv; ga.out[2] = Vh;
    dim3 gq(DM / 128, ROWS / 128, 3);   // (8, 32, 3)
    gemm_qkv3<<<gq, 256>>>(ga);

    // 3) flash attention
    dim3 gfl(S_LEN / 128, NH, B_SZ);    // (16, 16, 2)
    flash_attn_tc<<<gfl, 256, FL_SMEM>>>(Qh, Kh, Vh, Ch);

    // 4) output projection (fp32 out)
    dim3 go(DM / 128, ROWS / 128);      // (8, 32)
    gemm_out<<<go, 256>>>(Ch, Woh, bo, out);
}